// round 11
// baseline (speedup 1.0000x reference)
#include <cuda_runtime.h>
#include <cstdint>
#include <cstddef>

#define NORB   9
#define NATOMS 384
#define NEDGES 6144
#define NKP    4
#define ALLN   (NATOMS * NORB)              // 3456
#define NFEAT  58
#define KELEM  (ALLN * ALLN)                // 11,943,936 floats per k-region
#define NCPLX  ((size_t)NKP * KELEM)        // 47,775,744
#define NITEM  (NEDGES + NATOMS)            // 6528 work items
#define TWO_PI 6.283185307179586f

// Grid layout of the fused stage kernel: scatter blocks first (they have the
// longer critical path), then fill blocks.
#define NSCATB 1479                         // 1479*256 = 378,624 = 6528*58 exact
#define NFILLB 3072                         // 3072*256*4 float4 >= KELEM/4
#define NGRID  (NSCATB + NFILLB)

// Static feature -> (row, col, factor) maps for upper-tri orbital pairs
// l = [0,1,2], dims = [1,3,5], offsets = [0,1,4]
__constant__ unsigned char cROWS[NFEAT] = {
    0,
    0,0,0,
    0,0,0,0,0,
    1,1,1,2,2,2,3,3,3,
    1,1,1,1,1,2,2,2,2,2,3,3,3,3,3,
    4,4,4,4,4,5,5,5,5,5,6,6,6,6,6,7,7,7,7,7,8,8,8,8,8
};
__constant__ unsigned char cCOLS[NFEAT] = {
    0,
    1,2,3,
    4,5,6,7,8,
    1,2,3,1,2,3,1,2,3,
    4,5,6,7,8,4,5,6,7,8,4,5,6,7,8,
    4,5,6,7,8,4,5,6,7,8,4,5,6,7,8,4,5,6,7,8,4,5,6,7,8
};
__constant__ float cFACS[NFEAT] = {
    0.5f,
    1.f,1.f,1.f,
    1.f,1.f,1.f,1.f,1.f,
    0.5f,0.5f,0.5f,0.5f,0.5f,0.5f,0.5f,0.5f,0.5f,
    1.f,1.f,1.f,1.f,1.f,1.f,1.f,1.f,1.f,1.f,1.f,1.f,1.f,1.f,1.f,
    0.5f,0.5f,0.5f,0.5f,0.5f,0.5f,0.5f,0.5f,0.5f,0.5f,0.5f,0.5f,0.5f,
    0.5f,0.5f,0.5f,0.5f,0.5f,0.5f,0.5f,0.5f,0.5f,0.5f,0.5f,0.5f
};

// Fused pipeline stage: fill k-region `fillK` with zeros while scattering
// contributions into the (already zeroed) k-region `scatK`. The two halves
// touch disjoint 48 MB address ranges, so no intra-launch ordering is
// needed; stream order between launches provides fill->scatter per region.
__global__ __launch_bounds__(256) void hr2hk_stage(
    const float* __restrict__ hop,     // [E, 58]
    const float* __restrict__ ons,     // [N, 58]
    const float* __restrict__ kpts,    // [4, 3]
    const int*   __restrict__ eidx,    // [2, E]
    const int*   __restrict__ eshift,  // [E, 3]
    float*       __restrict__ out,     // [4, 3456, 3456] float32 (real part)
    int fillK, int scatK)
{
    if (blockIdx.x < NSCATB) {
        // ---- scatter into region scatK ----
        if (scatK < 0) return;
        const int t = blockIdx.x * 256 + threadIdx.x;   // exact: 6528*58
        const int w = t / NFEAT;
        const int f = t - w * NFEAT;
        const bool is_edge = (w < NEDGES);

        int ai, aj;
        float ph;                        // Re[exp(-2*pi*i k.R)]
        if (is_edge) {
            ai = eidx[w];
            aj = eidx[NEDGES + w];
            const float d = kpts[scatK * 3 + 0] * (float)eshift[w * 3 + 0]
                          + kpts[scatK * 3 + 1] * (float)eshift[w * 3 + 1]
                          + kpts[scatK * 3 + 2] * (float)eshift[w * 3 + 2];
            ph = __cosf(TWO_PI * d);
        } else {
            ai = w - NEDGES;
            aj = ai;
            ph = 1.f;
        }
        if ((unsigned)ai >= NATOMS || (unsigned)aj >= NATOMS) return;

        const float* __restrict__ src =
            is_edge ? (hop + (size_t)w * NFEAT)
                    : (ons + (size_t)(w - NEDGES) * NFEAT);
        const float v = cFACS[f] * src[f] * ph;

        const int r = ai * NORB + (int)cROWS[f];
        const int c = aj * NORB + (int)cCOLS[f];
        float* __restrict__ base = out + (size_t)scatK * KELEM;
        atomicAdd(base + (size_t)r * ALLN + c, v);   // Re(B)   at (r,c)
        atomicAdd(base + (size_t)c * ALLN + r, v);   // Re(B^H) at (c,r)
    } else {
        // ---- zero-fill region fillK ----
        if (fillK < 0) return;
        float4* __restrict__ dst = (float4*)(out + (size_t)fillK * KELEM);
        const int i = (blockIdx.x - NSCATB) * 256 + threadIdx.x;
        const float4 z = make_float4(0.f, 0.f, 0.f, 0.f);
        #pragma unroll
        for (int u = 0; u < 4; ++u) {
            const int idx = i + u * (NFILLB * 256);
            if (idx < KELEM / 4) dst[idx] = z;
        }
    }
}

// ---- complex64 fallback (unused for the f32 output; kept for safety) ----
__global__ __launch_bounds__(256, 8) void hr2hk_scatter_cplx(
    const float* __restrict__ hop, const float* __restrict__ ons,
    const float* __restrict__ kpts, const int* __restrict__ eidx,
    const int* __restrict__ eshift, float* __restrict__ out)
{
    const int w = blockIdx.x;
    const int t = threadIdx.x;
    if (t >= NFEAT * NKP) return;
    const int f = t >> 2;
    const int k = t & 3;
    const bool is_edge = (w < NEDGES);

    int ai, aj;
    float pre, pim;
    if (is_edge) {
        ai = eidx[w];
        aj = eidx[NEDGES + w];
        const float d = kpts[k * 3 + 0] * (float)eshift[w * 3 + 0]
                      + kpts[k * 3 + 1] * (float)eshift[w * 3 + 1]
                      + kpts[k * 3 + 2] * (float)eshift[w * 3 + 2];
        float s, c;
        __sincosf(TWO_PI * d, &s, &c);
        pre = c; pim = -s;
    } else {
        ai = w - NEDGES; aj = ai; pre = 1.f; pim = 0.f;
    }
    if ((unsigned)ai >= NATOMS || (unsigned)aj >= NATOMS) return;

    const float* __restrict__ src =
        is_edge ? (hop + (size_t)w * NFEAT)
                : (ons + (size_t)(w - NEDGES) * NFEAT);
    const float val = cFACS[f] * src[f];
    const float re = val * pre, im = val * pim;
    const int r = ai * NORB + (int)cROWS[f];
    const int c = aj * NORB + (int)cCOLS[f];
    const size_t kbase = (size_t)k * KELEM;
    float* p0 = out + 2 * (kbase + (size_t)r * ALLN + c);
    float* p1 = out + 2 * (kbase + (size_t)c * ALLN + r);
    atomicAdd(p0 + 0, re);
    atomicAdd(p0 + 1, im);
    atomicAdd(p1 + 0, re);
    atomicAdd(p1 + 1, -im);
}

__global__ void hr2hk_zero(uint4* __restrict__ out, size_t n_u4) {
    for (size_t i = (size_t)blockIdx.x * blockDim.x + threadIdx.x;
         i < n_u4; i += (size_t)gridDim.x * blockDim.x)
        out[i] = make_uint4(0u, 0u, 0u, 0u);
}

extern "C" void kernel_launch(void* const* d_in, const int* in_sizes, int n_in,
                              void* d_out, int out_size) {
    // Identify inputs by (pairwise-distinct) element counts, not position.
    const float* hop    = nullptr;
    const float* ons    = nullptr;
    const float* kpts   = nullptr;
    const int*   eidx   = nullptr;
    const int*   eshift = nullptr;

    for (int i = 0; i < n_in; ++i) {
        switch (in_sizes[i]) {
            case NEDGES * NFEAT: hop    = (const float*)d_in[i]; break;  // 356352
            case NATOMS * NFEAT: ons    = (const float*)d_in[i]; break;  // 22272
            case NKP * 3:        kpts   = (const float*)d_in[i]; break;  // 12
            case 2 * NEDGES:     eidx   = (const int*)d_in[i];   break;  // 12288
            case NEDGES * 3:     eshift = (const int*)d_in[i];   break;  // 18432
            default: break;
        }
    }
    if (!hop || !ons || !kpts || !eidx || !eshift) return;

    if ((long long)out_size == (long long)NCPLX) {
        // f32 real-part output: 5-stage fill/scatter software pipeline.
        float* o = (float*)d_out;
        hr2hk_stage<<<NGRID, 256>>>(hop, ons, kpts, eidx, eshift, o, 0, -1);
        hr2hk_stage<<<NGRID, 256>>>(hop, ons, kpts, eidx, eshift, o, 1,  0);
        hr2hk_stage<<<NGRID, 256>>>(hop, ons, kpts, eidx, eshift, o, 2,  1);
        hr2hk_stage<<<NGRID, 256>>>(hop, ons, kpts, eidx, eshift, o, 3,  2);
        hr2hk_stage<<<NGRID, 256>>>(hop, ons, kpts, eidx, eshift, o, -1, 3);
    } else if ((long long)out_size == 2LL * (long long)NCPLX) {
        hr2hk_zero<<<8192, 256>>>((uint4*)d_out, NCPLX * 8 / 16);
        hr2hk_scatter_cplx<<<NEDGES + NATOMS, 256>>>(
            hop, ons, kpts, eidx, eshift, (float*)d_out);
    }
}